// round 10
// baseline (speedup 1.0000x reference)
#include <cuda_runtime.h>
#include <cuda_bf16.h>

// relu(segment_sum(x @ W^T + b))  ==  relu(segment_sum(x) @ W^T + count * b)
// N=500000, H=256, B=1024, seg_ids sorted ascending.
//
// Pipeline:
//  1. segsum: row-major pooled via coalesced atomics  (~74us, HBM roofline)
//  2. prep:   transpose pooled -> PT[k][g] and W -> WT[k][j] (32x32 padded
//             smem tiles), snapshot counts, and ZERO pooled/count for the
//             next graph replay. PT/WT/countT are fully overwritten each
//             launch, so they need no zeroing and no arrival counters.
//  3. finish: shuffle-free, smem-free warp GEMM. warp = 32s x 8j, lane = s.
//             Per k: 1 coalesced LDG of PT (1 wavefront) + 2 uniform
//             broadcast LDG.128 of WT + 8 FFMA. (All lane-spans-k variants
//             paid a 32-line wavefront tax or an 80-SHFL tax -> 19.7us.)

#define H 256
#define HV 64                  // H/4
#define B 1024
#define TARGET_GRID 1184       // segsum: 148 SMs * 8 blocks ceiling
#define RPI 32                 // segsum rows per iteration

__device__ float g_pooled[B * H];        // [g][k] segment sums (zero-init)
__device__ float g_count[B];             // nodes per segment   (zero-init)
__device__ float g_pooledT[H * B];       // [k][g] (overwritten by prep)
__device__ float g_WT[H * H];            // [k][j] (overwritten by prep)
__device__ float g_countT[B];            // count snapshot (overwritten)

// ---------------------------------------------------------------------------
// Kernel 1: segment-sum of x (row-major pooled).  ~74us, at HBM roofline.
// ---------------------------------------------------------------------------
__device__ __forceinline__ void flush_acc(float4& acc, int cur, int c) {
    float* dst = &g_pooled[cur * H + c * 4];
    atomicAdd(dst + 0, acc.x);
    atomicAdd(dst + 1, acc.y);
    atomicAdd(dst + 2, acc.z);
    atomicAdd(dst + 3, acc.w);
    acc = make_float4(0.f, 0.f, 0.f, 0.f);
}

__global__ void __launch_bounds__(H) segsum_kernel(
    const float* __restrict__ x, const int* __restrict__ seg,
    int N, int rows_per_block)
{
    int r0 = blockIdx.x * rows_per_block;
    int r1 = min(r0 + rows_per_block, N);
    if (r0 >= r1) return;

    const int tid    = threadIdx.x;
    const int c      = tid & 63;
    const int rowoff = tid >> 6;
    const float4* __restrict__ x4 = reinterpret_cast<const float4*>(x);

    float4 acc = make_float4(0.f, 0.f, 0.f, 0.f);
    int cur       = __ldg(&seg[r0]);
    int run_start = r0;

    int r = r0;
    for (; r + RPI <= r1; r += RPI) {
        size_t base = (size_t)(r + rowoff) * HV + c;
        float4 v0 = __ldg(&x4[base + 0 * 4 * HV]);
        float4 v1 = __ldg(&x4[base + 1 * 4 * HV]);
        float4 v2 = __ldg(&x4[base + 2 * 4 * HV]);
        float4 v3 = __ldg(&x4[base + 3 * 4 * HV]);
        float4 v4 = __ldg(&x4[base + 4 * 4 * HV]);
        float4 v5 = __ldg(&x4[base + 5 * 4 * HV]);
        float4 v6 = __ldg(&x4[base + 6 * 4 * HV]);
        float4 v7 = __ldg(&x4[base + 7 * 4 * HV]);
        int s_last = __ldg(&seg[r + RPI - 1]);

        if (s_last == cur) {
            acc.x += ((v0.x + v1.x) + (v2.x + v3.x)) + ((v4.x + v5.x) + (v6.x + v7.x));
            acc.y += ((v0.y + v1.y) + (v2.y + v3.y)) + ((v4.y + v5.y) + (v6.y + v7.y));
            acc.z += ((v0.z + v1.z) + (v2.z + v3.z)) + ((v4.z + v5.z) + (v6.z + v7.z));
            acc.w += ((v0.w + v1.w) + (v2.w + v3.w)) + ((v4.w + v5.w) + (v6.w + v7.w));
        } else {
            float4 vv[8] = {v0, v1, v2, v3, v4, v5, v6, v7};
            #pragma unroll
            for (int k = 0; k < RPI; ++k) {
                int rr = r + k;
                int s = __ldg(&seg[rr]);
                if (s != cur) {
                    flush_acc(acc, cur, c);
                    if (tid == 0)
                        atomicAdd(&g_count[cur], (float)(rr - run_start));
                    cur = s; run_start = rr;
                }
                if ((k & 3) == rowoff) {
                    float4 v = vv[k >> 2];
                    acc.x += v.x; acc.y += v.y; acc.z += v.z; acc.w += v.w;
                }
            }
        }
    }
    for (; r < r1; ++r) {
        int s = __ldg(&seg[r]);
        if (s != cur) {
            flush_acc(acc, cur, c);
            if (tid == 0) atomicAdd(&g_count[cur], (float)(r - run_start));
            cur = s; run_start = r;
        }
        if (rowoff == 0) {
            float4 v = __ldg(&x4[(size_t)r * HV + c]);
            acc.x += v.x; acc.y += v.y; acc.z += v.z; acc.w += v.w;
        }
    }
    flush_acc(acc, cur, c);
    if (tid == 0) atomicAdd(&g_count[cur], (float)(r1 - run_start));
}

// ---------------------------------------------------------------------------
// Kernel 2: prep. Blocks 0..255: pooled 32x32 tile transpose -> PT, then
// zero that pooled tile; k-tile-0 blocks snapshot+zero counts.
// Blocks 256..319: W 32x32 tile transpose -> WT.
// ---------------------------------------------------------------------------
__global__ void __launch_bounds__(256) prep_kernel(const float* __restrict__ W)
{
    __shared__ float ts[32][33];
    const int t  = threadIdx.x;
    const int tx = t & 31;
    const int ty = t >> 5;              // 0..7
    const int b  = blockIdx.x;

    if (b < 256) {
        const int g0 = (b & 31) * 32;   // segment tile
        const int k0 = (b >> 5) * 32;   // k tile
        #pragma unroll
        for (int i = 0; i < 4; ++i)
            ts[ty + 8 * i][tx] = g_pooled[(size_t)(g0 + ty + 8 * i) * H + k0 + tx];
        __syncthreads();
        #pragma unroll
        for (int i = 0; i < 4; ++i)
            g_pooledT[(size_t)(k0 + ty + 8 * i) * B + g0 + tx] = ts[tx][ty + 8 * i];
        // zero the pooled tile we just consumed (sync above ordered all reads)
        {
            const int r = t >> 3, c = t & 7;
            reinterpret_cast<float4*>(&g_pooled[(size_t)(g0 + r) * H + k0])[c] =
                make_float4(0.f, 0.f, 0.f, 0.f);
        }
        if ((b >> 5) == 0 && t < 32) {
            g_countT[g0 + t] = g_count[g0 + t];
            g_count[g0 + t] = 0.f;
        }
    } else {
        const int wb = b - 256;
        const int j0 = (wb & 7) * 32;
        const int k0 = (wb >> 3) * 32;
        #pragma unroll
        for (int i = 0; i < 4; ++i)
            ts[ty + 8 * i][tx] = __ldg(&W[(size_t)(j0 + ty + 8 * i) * H + k0 + tx]);
        __syncthreads();
        #pragma unroll
        for (int i = 0; i < 4; ++i)
            g_WT[(size_t)(k0 + ty + 8 * i) * H + j0 + tx] = ts[tx][ty + 8 * i];
    }
}

// ---------------------------------------------------------------------------
// Kernel 3: finish. 256 blocks x 128 threads. Warp = 32s x 8j, lane = s.
// Per k: p = PT[k][s0+lane] (coalesced 128B, 1 wf)
//        w0,w1 = WT[k][j0..j0+8) (2 uniform broadcast LDG.128, L1-hit)
//        8 FFMA. No smem, no shuffles. Outputs: 2 STG.128 per thread.
// ---------------------------------------------------------------------------
__global__ void __launch_bounds__(128) finish_kernel(
    const float* __restrict__ bias, float* __restrict__ out)
{
    const int warp = threadIdx.x >> 5;
    const int lane = threadIdx.x & 31;
    const int s0   = (blockIdx.x & 31) * 32;           // 32 segments
    const int j0   = (blockIdx.x >> 5) * 32 + warp * 8; // 8 outputs

    const float*  __restrict__ pt  = g_pooledT + s0 + lane;                 // +k*B
    const float4* __restrict__ wt4 = reinterpret_cast<const float4*>(g_WT) + (j0 >> 2); // +k*HV

    const float4 b0 = __ldg(reinterpret_cast<const float4*>(bias) + (j0 >> 2));
    const float4 b1 = __ldg(reinterpret_cast<const float4*>(bias) + (j0 >> 2) + 1);
    const float cnt = g_countT[s0 + lane];

    float4 a0 = make_float4(cnt * b0.x, cnt * b0.y, cnt * b0.z, cnt * b0.w);
    float4 a1 = make_float4(cnt * b1.x, cnt * b1.y, cnt * b1.z, cnt * b1.w);

    #pragma unroll 8
    for (int k = 0; k < H; ++k) {
        const float  p  = __ldg(&pt[(size_t)k * B]);
        const float4 w0 = __ldg(&wt4[(size_t)k * HV]);
        const float4 w1 = __ldg(&wt4[(size_t)k * HV + 1]);
        a0.x += w0.x * p; a0.y += w0.y * p; a0.z += w0.z * p; a0.w += w0.w * p;
        a1.x += w1.x * p; a1.y += w1.y * p; a1.z += w1.z * p; a1.w += w1.w * p;
    }

    a0.x = fmaxf(a0.x, 0.f); a0.y = fmaxf(a0.y, 0.f);
    a0.z = fmaxf(a0.z, 0.f); a0.w = fmaxf(a0.w, 0.f);
    a1.x = fmaxf(a1.x, 0.f); a1.y = fmaxf(a1.y, 0.f);
    a1.z = fmaxf(a1.z, 0.f); a1.w = fmaxf(a1.w, 0.f);

    float4* o4 = reinterpret_cast<float4*>(out) + (size_t)(s0 + lane) * HV + (j0 >> 2);
    o4[0] = a0;
    o4[1] = a1;
}

// ---------------------------------------------------------------------------
// Launch
// ---------------------------------------------------------------------------
extern "C" void kernel_launch(void* const* d_in, const int* in_sizes, int n_in,
                              void* d_out, int out_size)
{
    const float* x   = (const float*)d_in[0];   // [N, 256]
    const int*   seg = (const int*)  d_in[1];   // [N]
    const float* W   = (const float*)d_in[2];   // [256, 256]
    const float* b   = (const float*)d_in[3];   // [256]
    float* out = (float*)d_out;                 // [1024, 256]

    const int N = in_sizes[0] / H;

    int rpb = (N + TARGET_GRID - 1) / TARGET_GRID;
    rpb = ((rpb + RPI - 1) / RPI) * RPI;        // N=500000 -> 448
    int grid = (N + rpb - 1) / rpb;             // -> 1117 (single wave)

    segsum_kernel<<<grid, H>>>(x, seg, N, rpb);
    prep_kernel<<<320, 256>>>(W);
    finish_kernel<<<256, 128>>>(b, out);
}

// round 11
// speedup vs baseline: 1.2111x; 1.2111x over previous
#include <cuda_runtime.h>
#include <cuda_bf16.h>

// relu(segment_sum(x @ W^T + b))  ==  relu(segment_sum(x) @ W^T + count * b)
// N=500000, H=256, B=1024, seg_ids sorted ascending.
//
// TWO kernels (per-kernel wall overhead in this rig is ~2-4us):
//  1. segsum: row-major pooled via coalesced atomics (77us, 85% DRAM --
//     at roofline, untouched). Its first 64 blocks also write
//     W4T[k4][j] = float4(W[j][4k4..]), a 256KB transposed copy of W
//     (coalesced writes; noise vs 512MB of x traffic).
//  2. finish: lane = j  ->  pooled reads are UNIFORM BROADCASTS from the
//     native row-major pooled (1 wavefront), W read coalesced from W4T.
//     No pooledT anywhere (both pooledT pipelines regressed: R8 201us,
//     R10 146us). No shuffles, no smem tiles, no arrival counters: each
//     block exclusively owns 8 segments and re-zeros them itself.

#define H 256
#define HV 64                  // H/4
#define B 1024
#define TARGET_GRID 1184       // segsum: 148 SMs * 8 blocks ceiling
#define RPI 32                 // segsum rows per iteration

__device__ float g_pooled[B * H];     // [g][k] segment sums (zero-init)
__device__ float g_count[B];          // nodes per segment   (zero-init)
__device__ float g_W4T[H * H];        // [k4][j] float4-transposed W
                                      // (fully overwritten every launch)

// ---------------------------------------------------------------------------
// Kernel 1: segment-sum of x (row-major pooled).  At HBM roofline.
// ---------------------------------------------------------------------------
__device__ __forceinline__ void flush_acc(float4& acc, int cur, int c) {
    float* dst = &g_pooled[cur * H + c * 4];
    atomicAdd(dst + 0, acc.x);
    atomicAdd(dst + 1, acc.y);
    atomicAdd(dst + 2, acc.z);
    atomicAdd(dst + 3, acc.w);
    acc = make_float4(0.f, 0.f, 0.f, 0.f);
}

__global__ void __launch_bounds__(H) segsum_kernel(
    const float* __restrict__ x, const int* __restrict__ seg,
    const float* __restrict__ W, int N, int rows_per_block)
{
    // ---- preamble: blocks 0..63 write the W4T transpose (one float4 each)
    // W4T[k4=blockIdx][j=tid] = W row j, float4 chunk k4.
    // Reads scattered (trivial: 256KB once), writes perfectly coalesced.
    if (blockIdx.x < 64) {
        reinterpret_cast<float4*>(g_W4T)[blockIdx.x * 256 + threadIdx.x] =
            __ldg(&reinterpret_cast<const float4*>(W)[threadIdx.x * HV + blockIdx.x]);
    }

    int r0 = blockIdx.x * rows_per_block;
    int r1 = min(r0 + rows_per_block, N);
    if (r0 >= r1) return;

    const int tid    = threadIdx.x;
    const int c      = tid & 63;
    const int rowoff = tid >> 6;
    const float4* __restrict__ x4 = reinterpret_cast<const float4*>(x);

    float4 acc = make_float4(0.f, 0.f, 0.f, 0.f);
    int cur       = __ldg(&seg[r0]);
    int run_start = r0;

    int r = r0;
    for (; r + RPI <= r1; r += RPI) {
        size_t base = (size_t)(r + rowoff) * HV + c;
        float4 v0 = __ldg(&x4[base + 0 * 4 * HV]);
        float4 v1 = __ldg(&x4[base + 1 * 4 * HV]);
        float4 v2 = __ldg(&x4[base + 2 * 4 * HV]);
        float4 v3 = __ldg(&x4[base + 3 * 4 * HV]);
        float4 v4 = __ldg(&x4[base + 4 * 4 * HV]);
        float4 v5 = __ldg(&x4[base + 5 * 4 * HV]);
        float4 v6 = __ldg(&x4[base + 6 * 4 * HV]);
        float4 v7 = __ldg(&x4[base + 7 * 4 * HV]);
        int s_last = __ldg(&seg[r + RPI - 1]);

        if (s_last == cur) {
            acc.x += ((v0.x + v1.x) + (v2.x + v3.x)) + ((v4.x + v5.x) + (v6.x + v7.x));
            acc.y += ((v0.y + v1.y) + (v2.y + v3.y)) + ((v4.y + v5.y) + (v6.y + v7.y));
            acc.z += ((v0.z + v1.z) + (v2.z + v3.z)) + ((v4.z + v5.z) + (v6.z + v7.z));
            acc.w += ((v0.w + v1.w) + (v2.w + v3.w)) + ((v4.w + v5.w) + (v6.w + v7.w));
        } else {
            float4 vv[8] = {v0, v1, v2, v3, v4, v5, v6, v7};
            #pragma unroll
            for (int k = 0; k < RPI; ++k) {
                int rr = r + k;
                int s = __ldg(&seg[rr]);
                if (s != cur) {
                    flush_acc(acc, cur, c);
                    if (tid == 0)
                        atomicAdd(&g_count[cur], (float)(rr - run_start));
                    cur = s; run_start = rr;
                }
                if ((k & 3) == rowoff) {
                    float4 v = vv[k >> 2];
                    acc.x += v.x; acc.y += v.y; acc.z += v.z; acc.w += v.w;
                }
            }
        }
    }
    for (; r < r1; ++r) {
        int s = __ldg(&seg[r]);
        if (s != cur) {
            flush_acc(acc, cur, c);
            if (tid == 0) atomicAdd(&g_count[cur], (float)(r - run_start));
            cur = s; run_start = r;
        }
        if (rowoff == 0) {
            float4 v = __ldg(&x4[(size_t)r * HV + c]);
            acc.x += v.x; acc.y += v.y; acc.z += v.z; acc.w += v.w;
        }
    }
    flush_acc(acc, cur, c);
    if (tid == 0) atomicAdd(&g_count[cur], (float)(r1 - run_start));
}

// ---------------------------------------------------------------------------
// Kernel 2: finish. 128 blocks x 256 threads. Block owns 8 segments;
// warp owns 32 j (lane = j). Per k4:
//   w    = W4T[k4][j]            1 coalesced LDG.128 (512B/warp, 4 wf)
//   p[s] = pooled[g0+s][k4]      8 uniform-broadcast LDG.128 (1 wf each,
//                                L1-resident: 8KB pooled slice per block)
//   32 FFMA per thread. No shuffles, no smem, no transposed pooled.
// Then: coalesced relu-stores, and the block re-zeros its own 8 pooled
// rows + counts (exclusive ownership -> no counters needed).
// ---------------------------------------------------------------------------
__global__ void __launch_bounds__(256) finish_kernel(
    const float* __restrict__ bias, float* __restrict__ out)
{
    const int t    = threadIdx.x;
    const int warp = t >> 5;
    const int lane = t & 31;
    const int g0   = blockIdx.x * 8;
    const int j    = warp * 32 + lane;

    const float4* __restrict__ p4  = reinterpret_cast<const float4*>(g_pooled);
    const float4* __restrict__ w4t = reinterpret_cast<const float4*>(g_W4T);

    float acc[8];
    {
        const float bj = __ldg(&bias[j]);
        #pragma unroll
        for (int s = 0; s < 8; ++s)
            acc[s] = g_count[g0 + s] * bj;
    }

    #pragma unroll 2
    for (int k4 = 0; k4 < HV; ++k4) {
        const float4 w = __ldg(&w4t[k4 * 256 + j]);
        #pragma unroll
        for (int s = 0; s < 8; ++s) {
            const float4 p = __ldg(&p4[(size_t)(g0 + s) * HV + k4]);
            acc[s] += w.x * p.x + w.y * p.y + w.z * p.z + w.w * p.w;
        }
    }

    #pragma unroll
    for (int s = 0; s < 8; ++s)
        out[(size_t)(g0 + s) * H + j] = fmaxf(acc[s], 0.f);

    // ---- re-zero this block's exclusively-owned scratch region ----
    __syncthreads();                    // all reads of pooled/count complete
    {
        const float4 z = make_float4(0.f, 0.f, 0.f, 0.f);
        float4* pz = reinterpret_cast<float4*>(g_pooled) + (size_t)g0 * HV;
        pz[t]       = z;                // 8 rows * 64 float4 = 512 = 2/thread
        pz[t + 256] = z;
        if (t < 8) g_count[g0 + t] = 0.f;
    }
}

// ---------------------------------------------------------------------------
// Launch
// ---------------------------------------------------------------------------
extern "C" void kernel_launch(void* const* d_in, const int* in_sizes, int n_in,
                              void* d_out, int out_size)
{
    const float* x   = (const float*)d_in[0];   // [N, 256]
    const int*   seg = (const int*)  d_in[1];   // [N]
    const float* W   = (const float*)d_in[2];   // [256, 256]
    const float* b   = (const float*)d_in[3];   // [256]
    float* out = (float*)d_out;                 // [1024, 256]

    const int N = in_sizes[0] / H;

    int rpb = (N + TARGET_GRID - 1) / TARGET_GRID;
    rpb = ((rpb + RPI - 1) / RPI) * RPI;        // N=500000 -> 448
    int grid = (N + rpb - 1) / rpb;             // -> 1117

    segsum_kernel<<<grid, H>>>(x, seg, W, N, rpb);
    finish_kernel<<<B / 8, 256>>>(b, out);
}

// round 12
// speedup vs baseline: 1.3972x; 1.1536x over previous
#include <cuda_runtime.h>
#include <cuda_bf16.h>

// relu(segment_sum(x @ W^T + b))  ==  relu(segment_sum(x) @ W^T + count * b)
// N=500000, H=256, B=1024, seg_ids sorted ascending.
//
// TWO kernels:
//  1. segsum: row-major pooled via coalesced atomics (77us, 85% DRAM =
//     roofline; untouched). First 64 blocks also write the 256KB k-major
//     copy W4T[k4][j] (coalesced writes, noise vs 512MB of x).
//  2. finish: wavefront-clean loads (coalesced W4T + uniform pooled
//     broadcasts), now at 512 blocks for latency coverage (R11's 128
//     blocks = 7 warps/SM was latency-starved at 45.8us).

#define H 256
#define HV 64                  // H/4
#define B 1024
#define TARGET_GRID 1184       // segsum: 148 SMs * 8 blocks ceiling
#define RPI 32                 // segsum rows per iteration
#define FJT 4                  // finish: j tiles (64 j each)
#define FST 128                // finish: seg tiles (8 segs each)

__device__ float g_pooled[B * H];     // [g][k] segment sums (zero-init)
__device__ float g_count[B];          // nodes per segment   (zero-init)
__device__ float g_W4T[H * H];        // [k4][j] k-major W (overwritten/launch)
__device__ unsigned int g_done[FST];  // per-seg-tile arrival counters (zero-init)

// ---------------------------------------------------------------------------
// Kernel 1: segment-sum of x (row-major pooled).  At HBM roofline.
// ---------------------------------------------------------------------------
__device__ __forceinline__ void flush_acc(float4& acc, int cur, int c) {
    float* dst = &g_pooled[cur * H + c * 4];
    atomicAdd(dst + 0, acc.x);
    atomicAdd(dst + 1, acc.y);
    atomicAdd(dst + 2, acc.z);
    atomicAdd(dst + 3, acc.w);
    acc = make_float4(0.f, 0.f, 0.f, 0.f);
}

__global__ void __launch_bounds__(H) segsum_kernel(
    const float* __restrict__ x, const int* __restrict__ seg,
    const float* __restrict__ W, int N, int rows_per_block)
{
    // preamble: blocks 0..63 write W4T[k4=blockIdx][j=tid] (one float4 each)
    if (blockIdx.x < 64) {
        reinterpret_cast<float4*>(g_W4T)[blockIdx.x * 256 + threadIdx.x] =
            __ldg(&reinterpret_cast<const float4*>(W)[threadIdx.x * HV + blockIdx.x]);
    }

    int r0 = blockIdx.x * rows_per_block;
    int r1 = min(r0 + rows_per_block, N);
    if (r0 >= r1) return;

    const int tid    = threadIdx.x;
    const int c      = tid & 63;
    const int rowoff = tid >> 6;
    const float4* __restrict__ x4 = reinterpret_cast<const float4*>(x);

    float4 acc = make_float4(0.f, 0.f, 0.f, 0.f);
    int cur       = __ldg(&seg[r0]);
    int run_start = r0;

    int r = r0;
    for (; r + RPI <= r1; r += RPI) {
        size_t base = (size_t)(r + rowoff) * HV + c;
        float4 v0 = __ldg(&x4[base + 0 * 4 * HV]);
        float4 v1 = __ldg(&x4[base + 1 * 4 * HV]);
        float4 v2 = __ldg(&x4[base + 2 * 4 * HV]);
        float4 v3 = __ldg(&x4[base + 3 * 4 * HV]);
        float4 v4 = __ldg(&x4[base + 4 * 4 * HV]);
        float4 v5 = __ldg(&x4[base + 5 * 4 * HV]);
        float4 v6 = __ldg(&x4[base + 6 * 4 * HV]);
        float4 v7 = __ldg(&x4[base + 7 * 4 * HV]);
        int s_last = __ldg(&seg[r + RPI - 1]);

        if (s_last == cur) {
            acc.x += ((v0.x + v1.x) + (v2.x + v3.x)) + ((v4.x + v5.x) + (v6.x + v7.x));
            acc.y += ((v0.y + v1.y) + (v2.y + v3.y)) + ((v4.y + v5.y) + (v6.y + v7.y));
            acc.z += ((v0.z + v1.z) + (v2.z + v3.z)) + ((v4.z + v5.z) + (v6.z + v7.z));
            acc.w += ((v0.w + v1.w) + (v2.w + v3.w)) + ((v4.w + v5.w) + (v6.w + v7.w));
        } else {
            float4 vv[8] = {v0, v1, v2, v3, v4, v5, v6, v7};
            #pragma unroll
            for (int k = 0; k < RPI; ++k) {
                int rr = r + k;
                int s = __ldg(&seg[rr]);
                if (s != cur) {
                    flush_acc(acc, cur, c);
                    if (tid == 0)
                        atomicAdd(&g_count[cur], (float)(rr - run_start));
                    cur = s; run_start = rr;
                }
                if ((k & 3) == rowoff) {
                    float4 v = vv[k >> 2];
                    acc.x += v.x; acc.y += v.y; acc.z += v.z; acc.w += v.w;
                }
            }
        }
    }
    for (; r < r1; ++r) {
        int s = __ldg(&seg[r]);
        if (s != cur) {
            flush_acc(acc, cur, c);
            if (tid == 0) atomicAdd(&g_count[cur], (float)(r - run_start));
            cur = s; run_start = r;
        }
        if (rowoff == 0) {
            float4 v = __ldg(&x4[(size_t)r * HV + c]);
            acc.x += v.x; acc.y += v.y; acc.z += v.z; acc.w += v.w;
        }
    }
    flush_acc(acc, cur, c);
    if (tid == 0) atomicAdd(&g_count[cur], (float)(r1 - run_start));
}

// ---------------------------------------------------------------------------
// Kernel 2: finish. 512 blocks x 256 threads (4 j-tiles x 128 seg-tiles).
// Thread: j = j0 + (t&63), two segments (sh = t>>6 -> g0+sh*2, +1).
// Per k4: w = W4T[k4][j]  coalesced LDG.128 (4 wf/warp)
//         pa,pb           uniform broadcast LDG.128 (1 wf each, L1/L2-hit)
//         8 FFMA. No smem, no shuffles, no transposed pooled.
// Last of the 4 j-tile blocks per seg-tile re-zeros its 8 pooled rows.
// ---------------------------------------------------------------------------
__global__ void __launch_bounds__(256) finish_kernel(
    const float* __restrict__ bias, float* __restrict__ out)
{
    const int t  = threadIdx.x;
    const int jt = blockIdx.x & (FJT - 1);
    const int st = blockIdx.x >> 2;
    const int j  = jt * 64 + (t & 63);
    const int g0 = st * 8;
    const int ga = g0 + (t >> 6) * 2;
    const int gb = ga + 1;

    const float4* __restrict__ p4  = reinterpret_cast<const float4*>(g_pooled);
    const float4* __restrict__ w4t = reinterpret_cast<const float4*>(g_W4T);
    const float4* __restrict__ pa4 = p4 + (size_t)ga * HV;
    const float4* __restrict__ pb4 = p4 + (size_t)gb * HV;

    const float bj = __ldg(&bias[j]);
    float acca = g_count[ga] * bj;
    float accb = g_count[gb] * bj;

    #pragma unroll 4
    for (int k4 = 0; k4 < HV; ++k4) {
        const float4 w  = __ldg(&w4t[k4 * 256 + j]);
        const float4 pa = __ldg(&pa4[k4]);
        const float4 pb = __ldg(&pb4[k4]);
        acca += w.x * pa.x + w.y * pa.y + w.z * pa.z + w.w * pa.w;
        accb += w.x * pb.x + w.y * pb.y + w.z * pb.z + w.w * pb.w;
    }

    out[(size_t)ga * H + j] = fmaxf(acca, 0.f);
    out[(size_t)gb * H + j] = fmaxf(accb, 0.f);

    // ---- last of the 4 sibling blocks re-zeros this seg-tile's scratch ----
    __shared__ int s_last;
    __syncthreads();                    // all pooled/count reads complete
    if (t == 0) {
        __threadfence();
        s_last = (atomicAdd(&g_done[st], 1u) == FJT - 1) ? 1 : 0;
    }
    __syncthreads();
    if (s_last) {
        const float4 z = make_float4(0.f, 0.f, 0.f, 0.f);
        float4* pz = reinterpret_cast<float4*>(g_pooled) + (size_t)g0 * HV;
        pz[t]       = z;                // 8 rows * 64 float4 = 512 = 2/thread
        pz[t + 256] = z;
        if (t < 8) g_count[g0 + t] = 0.f;
        if (t == 0) g_done[st] = 0u;
    }
}

// ---------------------------------------------------------------------------
// Launch
// ---------------------------------------------------------------------------
extern "C" void kernel_launch(void* const* d_in, const int* in_sizes, int n_in,
                              void* d_out, int out_size)
{
    const float* x   = (const float*)d_in[0];   // [N, 256]
    const int*   seg = (const int*)  d_in[1];   // [N]
    const float* W   = (const float*)d_in[2];   // [256, 256]
    const float* b   = (const float*)d_in[3];   // [256]
    float* out = (float*)d_out;                 // [1024, 256]

    const int N = in_sizes[0] / H;

    int rpb = (N + TARGET_GRID - 1) / TARGET_GRID;
    rpb = ((rpb + RPI - 1) / RPI) * RPI;        // N=500000 -> 448
    int grid = (N + rpb - 1) / rpb;             // -> 1117

    segsum_kernel<<<grid, H>>>(x, seg, W, N, rpb);
    finish_kernel<<<FJT * FST, 256>>>(b, out);
}

// round 13
// speedup vs baseline: 1.5426x; 1.1041x over previous
#include <cuda_runtime.h>
#include <cuda_bf16.h>

// relu(segment_sum(x @ W^T + b))  ==  relu(segment_sum(x) @ W^T + count * b)
// N=500000, H=256, B=1024, seg_ids sorted ascending.
//
// TWO kernels:
//  1. segsum: row-major pooled via coalesced atomics (77us, 85% DRAM =
//     roofline; untouched). First 64 blocks also write the 256KB k-major
//     copy W4T[k4][j] (coalesced writes, noise vs 512MB of x).
//  2. finish: W tile staged in smem (29-cyc LDS kills the 250-cyc LDG
//     chain R12 died on), pooled via EXPLICIT NAMED uniform LDGs (8 in
//     flight -- ptxas kept MLP=3 with pragma-unroll arrays, regs=40).

#define H 256
#define HV 64                  // H/4
#define B 1024
#define TARGET_GRID 1184       // segsum: 148 SMs * 8 blocks ceiling
#define RPI 32                 // segsum rows per iteration
#define FJT 8                  // finish: j tiles (32 j each)
#define FST 64                 // finish: seg tiles (16 segs each)

__device__ float g_pooled[B * H];     // [g][k] segment sums (zero-init)
__device__ float g_count[B];          // nodes per segment   (zero-init)
__device__ float g_W4T[H * H];        // [k4][j] k-major W (overwritten/launch)
__device__ unsigned int g_done[FST];  // per-seg-tile arrival counters (zero-init)

// ---------------------------------------------------------------------------
// Kernel 1: segment-sum of x (row-major pooled).  At HBM roofline.
// ---------------------------------------------------------------------------
__device__ __forceinline__ void flush_acc(float4& acc, int cur, int c) {
    float* dst = &g_pooled[cur * H + c * 4];
    atomicAdd(dst + 0, acc.x);
    atomicAdd(dst + 1, acc.y);
    atomicAdd(dst + 2, acc.z);
    atomicAdd(dst + 3, acc.w);
    acc = make_float4(0.f, 0.f, 0.f, 0.f);
}

__global__ void __launch_bounds__(H) segsum_kernel(
    const float* __restrict__ x, const int* __restrict__ seg,
    const float* __restrict__ W, int N, int rows_per_block)
{
    // preamble: blocks 0..63 write W4T[k4=blockIdx][j=tid] (one float4 each)
    if (blockIdx.x < 64) {
        reinterpret_cast<float4*>(g_W4T)[blockIdx.x * 256 + threadIdx.x] =
            __ldg(&reinterpret_cast<const float4*>(W)[threadIdx.x * HV + blockIdx.x]);
    }

    int r0 = blockIdx.x * rows_per_block;
    int r1 = min(r0 + rows_per_block, N);
    if (r0 >= r1) return;

    const int tid    = threadIdx.x;
    const int c      = tid & 63;
    const int rowoff = tid >> 6;
    const float4* __restrict__ x4 = reinterpret_cast<const float4*>(x);

    float4 acc = make_float4(0.f, 0.f, 0.f, 0.f);
    int cur       = __ldg(&seg[r0]);
    int run_start = r0;

    int r = r0;
    for (; r + RPI <= r1; r += RPI) {
        size_t base = (size_t)(r + rowoff) * HV + c;
        float4 v0 = __ldg(&x4[base + 0 * 4 * HV]);
        float4 v1 = __ldg(&x4[base + 1 * 4 * HV]);
        float4 v2 = __ldg(&x4[base + 2 * 4 * HV]);
        float4 v3 = __ldg(&x4[base + 3 * 4 * HV]);
        float4 v4 = __ldg(&x4[base + 4 * 4 * HV]);
        float4 v5 = __ldg(&x4[base + 5 * 4 * HV]);
        float4 v6 = __ldg(&x4[base + 6 * 4 * HV]);
        float4 v7 = __ldg(&x4[base + 7 * 4 * HV]);
        int s_last = __ldg(&seg[r + RPI - 1]);

        if (s_last == cur) {
            acc.x += ((v0.x + v1.x) + (v2.x + v3.x)) + ((v4.x + v5.x) + (v6.x + v7.x));
            acc.y += ((v0.y + v1.y) + (v2.y + v3.y)) + ((v4.y + v5.y) + (v6.y + v7.y));
            acc.z += ((v0.z + v1.z) + (v2.z + v3.z)) + ((v4.z + v5.z) + (v6.z + v7.z));
            acc.w += ((v0.w + v1.w) + (v2.w + v3.w)) + ((v4.w + v5.w) + (v6.w + v7.w));
        } else {
            float4 vv[8] = {v0, v1, v2, v3, v4, v5, v6, v7};
            #pragma unroll
            for (int k = 0; k < RPI; ++k) {
                int rr = r + k;
                int s = __ldg(&seg[rr]);
                if (s != cur) {
                    flush_acc(acc, cur, c);
                    if (tid == 0)
                        atomicAdd(&g_count[cur], (float)(rr - run_start));
                    cur = s; run_start = rr;
                }
                if ((k & 3) == rowoff) {
                    float4 v = vv[k >> 2];
                    acc.x += v.x; acc.y += v.y; acc.z += v.z; acc.w += v.w;
                }
            }
        }
    }
    for (; r < r1; ++r) {
        int s = __ldg(&seg[r]);
        if (s != cur) {
            flush_acc(acc, cur, c);
            if (tid == 0) atomicAdd(&g_count[cur], (float)(r - run_start));
            cur = s; run_start = r;
        }
        if (rowoff == 0) {
            float4 v = __ldg(&x4[(size_t)r * HV + c]);
            acc.x += v.x; acc.y += v.y; acc.z += v.z; acc.w += v.w;
        }
    }
    flush_acc(acc, cur, c);
    if (tid == 0) atomicAdd(&g_count[cur], (float)(r1 - run_start));
}

// ---------------------------------------------------------------------------
// Kernel 2: finish. 512 blocks (8 jt x 64 st) x 128 threads.
// smem: 32KB W tile sws[k4][jl] (float4), staged coalesced, conflict-free.
// Thread: jl = t&31 (one j), warp = t>>5 picks 4 segments (S=4).
// Body (2 k4): 2 LDS.128 (W, 29cyc) + 8 EXPLICIT NAMED uniform LDGs
// (pooled, MLP=8 forced) + 64 FFMA. Warp lanes span 32 consecutive j ->
// LDS conflict-free, stores coalesced.
// Last of the 8 jt siblings per seg-tile re-zeros its scratch region.
// ---------------------------------------------------------------------------
__global__ void __launch_bounds__(128) finish_kernel(
    const float* __restrict__ bias, float* __restrict__ out)
{
    const int t  = threadIdx.x;
    const int jt = blockIdx.x & (FJT - 1);
    const int st = blockIdx.x >> 3;
    const int j0 = jt * 32;
    const int g0 = st * 16;
    const int jl = t & 31;
    const int sq = t >> 5;              // warp id = segment quad
    const int ga = g0 + sq * 4;

    __shared__ __align__(16) float4 sws[HV * 32];   // 32KB: sws[k4*32 + jl]

    // ---- stage W4T tile for j in [j0, j0+32): coalesced, conflict-free ----
    {
        const float4* __restrict__ w4t = reinterpret_cast<const float4*>(g_W4T);
        #pragma unroll
        for (int i = 0; i < 16; ++i) {
            int idx = t + i * 128;              // 0..2047
            int k4  = idx >> 5;
            int jj  = idx & 31;
            sws[idx] = __ldg(&w4t[k4 * 256 + j0 + jj]);
        }
    }
    __syncthreads();

    const float4* __restrict__ p4 = reinterpret_cast<const float4*>(g_pooled);
    const float4* __restrict__ pA = p4 + (size_t)(ga + 0) * HV;
    const float4* __restrict__ pB = p4 + (size_t)(ga + 1) * HV;
    const float4* __restrict__ pC = p4 + (size_t)(ga + 2) * HV;
    const float4* __restrict__ pD = p4 + (size_t)(ga + 3) * HV;

    const float bj = __ldg(&bias[j0 + jl]);
    float accA = g_count[ga + 0] * bj;
    float accB = g_count[ga + 1] * bj;
    float accC = g_count[ga + 2] * bj;
    float accD = g_count[ga + 3] * bj;

    for (int k4 = 0; k4 < HV; k4 += 2) {
        // explicit named loads: 2 LDS + 8 uniform LDG all in flight
        float4 w0 = sws[(k4 + 0) * 32 + jl];
        float4 w1 = sws[(k4 + 1) * 32 + jl];
        float4 a0 = __ldg(&pA[k4]);  float4 a1 = __ldg(&pA[k4 + 1]);
        float4 b0 = __ldg(&pB[k4]);  float4 b1 = __ldg(&pB[k4 + 1]);
        float4 c0 = __ldg(&pC[k4]);  float4 c1 = __ldg(&pC[k4 + 1]);
        float4 d0 = __ldg(&pD[k4]);  float4 d1 = __ldg(&pD[k4 + 1]);

        accA += w0.x * a0.x + w0.y * a0.y + w0.z * a0.z + w0.w * a0.w
              + w1.x * a1.x + w1.y * a1.y + w1.z * a1.z + w1.w * a1.w;
        accB += w0.x * b0.x + w0.y * b0.y + w0.z * b0.z + w0.w * b0.w
              + w1.x * b1.x + w1.y * b1.y + w1.z * b1.z + w1.w * b1.w;
        accC += w0.x * c0.x + w0.y * c0.y + w0.z * c0.z + w0.w * c0.w
              + w1.x * c1.x + w1.y * c1.y + w1.z * c1.z + w1.w * c1.w;
        accD += w0.x * d0.x + w0.y * d0.y + w0.z * d0.z + w0.w * d0.w
              + w1.x * d1.x + w1.y * d1.y + w1.z * d1.z + w1.w * d1.w;
    }

    const int j = j0 + jl;
    out[(size_t)(ga + 0) * H + j] = fmaxf(accA, 0.f);
    out[(size_t)(ga + 1) * H + j] = fmaxf(accB, 0.f);
    out[(size_t)(ga + 2) * H + j] = fmaxf(accC, 0.f);
    out[(size_t)(ga + 3) * H + j] = fmaxf(accD, 0.f);

    // ---- last of the 8 jt siblings re-zeros this seg-tile's scratch ----
    __shared__ int s_last;
    __syncthreads();                    // all pooled/count reads complete
    if (t == 0) {
        __threadfence();
        s_last = (atomicAdd(&g_done[st], 1u) == FJT - 1) ? 1 : 0;
    }
    __syncthreads();
    if (s_last) {
        const float4 z = make_float4(0.f, 0.f, 0.f, 0.f);
        float4* pz = reinterpret_cast<float4*>(g_pooled) + (size_t)g0 * HV;
        #pragma unroll
        for (int i = 0; i < 8; ++i)     // 16 segs * 64 float4 = 1024
            pz[t + i * 128] = z;
        if (t < 16) g_count[g0 + t] = 0.f;
        if (t == 0) g_done[st] = 0u;
    }
}

// ---------------------------------------------------------------------------
// Launch
// ---------------------------------------------------------------------------
extern "C" void kernel_launch(void* const* d_in, const int* in_sizes, int n_in,
                              void* d_out, int out_size)
{
    const float* x   = (const float*)d_in[0];   // [N, 256]
    const int*   seg = (const int*)  d_in[1];   // [N]
    const float* W   = (const float*)d_in[2];   // [256, 256]
    const float* b   = (const float*)d_in[3];   // [256]
    float* out = (float*)d_out;                 // [1024, 256]

    const int N = in_sizes[0] / H;

    int rpb = (N + TARGET_GRID - 1) / TARGET_GRID;
    rpb = ((rpb + RPI - 1) / RPI) * RPI;        // N=500000 -> 448
    int grid = (N + rpb - 1) / rpb;             // -> 1117

    segsum_kernel<<<grid, H>>>(x, seg, W, N, rpb);
    finish_kernel<<<FJT * FST, 128>>>(b, out);
}